// round 11
// baseline (speedup 1.0000x reference)
#include <cuda_runtime.h>
#include <cuda_bf16.h>
#include <cstdint>

// AttentionLayer_50989851738889
//
// Mathematical reduction (verified bit-exact, rel_err = 0.0 across rounds):
//   a = e / sum(e, axis=-1, keepdims=True) over a SIZE-1 axis -> a = e/e = 1.0
//   exactly (g bounded => e finite nonzero; IEEE x/x == 1.0).
//   v = a * inputs == inputs bit-for-bit. Output is a pure copy of d_in[0]
//   (B*L*D = 2097152 fp32 = 8 MB).
//
// Measured MLP curve (kernel-internal): MLP=1 -> 6.21us, MLP=4 -> 5.89us,
// MLP=8 -> 5.76us; graph memcpy node -> 7.65us total (dead end). Duration is
// ~T_ovh(≈5000cyc)-dominated at replay clocks with L2-hot data. Final curve
// point under test (3rd submission; prior two lost to broker timeouts):
// MLP=16 @ 128 CTAs. 128 x 256 x 16 float4 = 524288 exact, single wave.

__global__ void __launch_bounds__(256) copy_kernel_v4x16(
    const float4* __restrict__ src, float4* __restrict__ dst, int n4) {
    const int t = blockIdx.x * blockDim.x + threadIdx.x;
    const int s = gridDim.x * blockDim.x;  // 32768

    if (16 * s == n4) {
        float4 r[16];
        #pragma unroll
        for (int i = 0; i < 16; i++) r[i] = src[t + i * s];  // 16 batched LDG.128
        #pragma unroll
        for (int i = 0; i < 16; i++) dst[t + i * s] = r[i];
    } else {
        // Generic fallback (never taken for the fixed shape)
        for (int i = t; i < n4; i += s) dst[i] = src[i];
    }
}

extern "C" void kernel_launch(void* const* d_in, const int* in_sizes, int n_in,
                              void* d_out, int out_size) {
    const float4* src = (const float4*)d_in[0];
    float4* dst = (float4*)d_out;

    int n4 = out_size >> 2;  // 524288 float4

    const int threads = 256;
    const int blocks = 128;  // 128*256*16 == 524288 exactly; single wave
    copy_kernel_v4x16<<<blocks, threads>>>(src, dst, n4);
}

// round 12
// speedup vs baseline: 1.0048x; 1.0048x over previous
#include <cuda_runtime.h>
#include <cuda_bf16.h>
#include <cstdint>

// AttentionLayer_50989851738889
//
// Mathematical reduction (verified bit-exact, rel_err = 0.0 across rounds):
//   a = e / sum(e, axis=-1, keepdims=True) over a SIZE-1 axis -> a = e/e = 1.0
//   exactly (g bounded => e finite nonzero; IEEE x/x == 1.0).
//   v = a * inputs == inputs bit-for-bit. Output is a pure copy of d_in[0]
//   (B*L*D = 2097152 fp32 = 8 MB).
//
// Measured curve (kernel-internal): MLP=1/2048CTA 6.21us; MLP=4/512CTA
// 5.89us; MLP=8/256CTA 5.76us (best); MLP=16/128CTA 6.24us (REGRESSED:
// grid < 148 SMs left 20 SMs idle); graph memcpy node 7.65us (dead end).
// Totals all 6.62-6.66us; ~0.9us is graph-replay overhead. Final interior
// point: MLP=8 with 512 CTAs x 128 threads — same batch depth, full SM
// coverage at ~3.5 CTAs/SM for a shorter straggler tail.

__global__ void __launch_bounds__(128) copy_kernel_v4x8_b128(
    const float4* __restrict__ src, float4* __restrict__ dst, int n4) {
    const int t = blockIdx.x * blockDim.x + threadIdx.x;
    const int s = gridDim.x * blockDim.x;  // 65536

    if (8 * s == n4) {
        // 8 independent front-batched LDG.128 per thread
        float4 r0 = src[t];
        float4 r1 = src[t + s];
        float4 r2 = src[t + 2 * s];
        float4 r3 = src[t + 3 * s];
        float4 r4 = src[t + 4 * s];
        float4 r5 = src[t + 5 * s];
        float4 r6 = src[t + 6 * s];
        float4 r7 = src[t + 7 * s];
        dst[t]         = r0;
        dst[t + s]     = r1;
        dst[t + 2 * s] = r2;
        dst[t + 3 * s] = r3;
        dst[t + 4 * s] = r4;
        dst[t + 5 * s] = r5;
        dst[t + 6 * s] = r6;
        dst[t + 7 * s] = r7;
    } else {
        // Generic fallback (never taken for the fixed shape)
        for (int i = t; i < n4; i += s) dst[i] = src[i];
    }
}

extern "C" void kernel_launch(void* const* d_in, const int* in_sizes, int n_in,
                              void* d_out, int out_size) {
    const float4* src = (const float4*)d_in[0];
    float4* dst = (float4*)d_out;

    int n4 = out_size >> 2;  // 524288 float4

    const int threads = 128;
    const int blocks = 512;  // 512*128*8 == 524288 exactly; single wave, all SMs
    copy_kernel_v4x8_b128<<<blocks, threads>>>(src, dst, n4);
}